// round 13
// baseline (speedup 1.0000x reference)
#include <cuda_runtime.h>
#include <cuda_fp16.h>

#define NN 50000
#define FF 16
#define EE 800000
#define HH 64
#define TOUT 10
#define NF (NN*FF)

// ---------------- device state ----------------
__device__ float   g_x0[NF];
__device__ float   g_xi[NF];
__device__ float   g_k[6][NF];
__device__ __half2 g_uv[2][NN*32];   // packed u: (.x=ch lane, .y=ch lane+32), double-buffered
__device__ float   g_v[NN*HH];
__device__ float   g_augproj[NN*HH];
__device__ float   g_ys[TOUT*NF];
__device__ int     g_deg[NN];
__device__ int     g_rowptr[NN+1];
__device__ int     g_wptr[NN];
__device__ int     g_src_sorted[EE];
__device__ __half2 g_eaw[EE*32];     // precomputed ea@Wea per edge, CSR order, half2 ch-pairs

// DOPRI5 coefficients. Row 0 unused, rows 1..5 = A[0..4], row 6 = B.
__constant__ float c_coef[7][6] = {
  {0.f,0.f,0.f,0.f,0.f,0.f},
  {(float)(0.2), 0.f,0.f,0.f,0.f,0.f},
  {(float)(3.0/40.0), (float)(9.0/40.0), 0.f,0.f,0.f,0.f},
  {(float)(44.0/45.0), (float)(-56.0/15.0), (float)(32.0/9.0), 0.f,0.f,0.f},
  {(float)(19372.0/6561.0), (float)(-25360.0/2187.0), (float)(64448.0/6561.0), (float)(-212.0/729.0), 0.f,0.f},
  {(float)(9017.0/3168.0), (float)(-355.0/33.0), (float)(46732.0/5247.0), (float)(49.0/176.0), (float)(-5103.0/18656.0), 0.f},
  {(float)(35.0/384.0), 0.f, (float)(500.0/1113.0), (float)(125.0/192.0), (float)(-2187.0/6784.0), (float)(11.0/84.0)}
};
__constant__ float c_C[6] = {0.f, 0.2f, 0.3f, 0.8f, (float)(8.0/9.0), 1.f};

__device__ __forceinline__ float tanha(float x) {
  float r;
  asm("tanh.approx.f32 %0, %1;" : "=f"(r) : "f"(x));
  return r;
}

// ---------------- launch 1: combo = state init + augproj + u/v projection + deg zero ----------------
__global__ __launch_bounds__(256) void combo_kernel(
    const float* __restrict__ xh, const float* __restrict__ xm,
    const float* __restrict__ W1m, const float* __restrict__ b1m,
    const float* __restrict__ W1n, const float* __restrict__ b1n)
{
  __shared__ float saug[4][176];
  __shared__ float sW[32 * 64];
  __shared__ float sxi[4][16];
  __shared__ float sb[64];
  int b = blockIdx.x;
  int tid = threadIdx.x;
  int gid = b * 256 + tid;
  if (gid < NN) g_deg[gid] = 0;
  int ln = tid >> 6;
  int ch = tid & 63;
  int n = b * 4 + ln;
  #pragma unroll
  for (int i = tid; i < 512; i += 256) ((float4*)sW)[i] = ((const float4*)W1m)[i];
  if (tid < 16) ((float4*)sb)[tid] = ((const float4*)b1m)[tid];
  if (ch < 16) {
    int f = ch;
    float xs[10], ms[10];
    float sm = 0.f, cm = 0.f;
    #pragma unroll
    for (int tt = 0; tt < 10; tt++) {
      xs[tt] = xh[(tt * NN + n) * FF + f];
      ms[tt] = xm[tt * NN + n];
      sm += xs[tt] * ms[tt];
      cm += ms[tt];
    }
    float cnt = fmaxf(cm, 1.0f);
    float mean = sm / cnt;
    float var = 0.f;
    #pragma unroll
    for (int tt = 0; tt < 10; tt++) { float d = xs[tt] - mean; var += d * d * ms[tt]; }
    var /= cnt;
    #pragma unroll
    for (int tt = 0; tt < 9; tt++)
      saug[ln][tt * 16 + f] = (xs[tt + 1] - xs[tt]) * (ms[tt + 1] * ms[tt]);
    saug[ln][144 + f] = mean;
    saug[ln][160 + f] = var;
    int idx = n * 16 + f;
    float xv = xs[9];
    g_x0[idx] = xv;
    g_xi[idx] = xv;
    sxi[ln][f] = xv;
  }
  __syncthreads();
  {
    float acc = b1n[ch];
    #pragma unroll 8
    for (int r = 0; r < 176; r++)
      acc += saug[ln][r] * W1n[(32 + r) * 64 + ch];
    g_augproj[n * 64 + ch] = acc;
  }
  if (ch < 32) {
    int lane = ch;
    float u0 = 0.f, u1 = 0.f;
    float v0 = sb[lane], v1 = sb[32 + lane];
    #pragma unroll
    for (int i = 0; i < 16; i++) {
      float xv = sxi[ln][i];
      u0 += xv * sW[i * 64 + lane];
      u1 += xv * sW[i * 64 + 32 + lane];
      v0 += xv * sW[(16 + i) * 64 + lane];
      v1 += xv * sW[(16 + i) * 64 + 32 + lane];
    }
    g_uv[0][n * 32 + lane] = __floats2half2_rn(u0, u1);
    g_v[n * 64 + lane] = v0;
    g_v[n * 64 + 32 + lane] = v1;
  }
}

// ---------------- launch 2: single-block histogram + rowptr scan ----------------
__global__ __launch_bounds__(1024) void histscan_kernel(const int* __restrict__ ei) {
  __shared__ int wsum[32];
  int tid = threadIdx.x, lane = tid & 31, wid = tid >> 5;
  for (int e = tid; e < EE; e += 1024)
    atomicAdd(&g_deg[ei[EE + e]], 1);
  __syncthreads();
  int carry = 0;
  for (int base = 0; base < NN; base += 1024) {
    int i = base + tid;
    int v = (i < NN) ? g_deg[i] : 0;
    int x = v;
    #pragma unroll
    for (int o = 1; o < 32; o <<= 1) { int y = __shfl_up_sync(0xffffffffu, x, o); if (lane >= o) x += y; }
    if (lane == 31) wsum[wid] = x;
    __syncthreads();
    if (wid == 0) {
      int s = wsum[lane];
      #pragma unroll
      for (int o = 1; o < 32; o <<= 1) { int y = __shfl_up_sync(0xffffffffu, s, o); if (lane >= o) s += y; }
      wsum[lane] = s;
    }
    __syncthreads();
    int incl = x + carry + (wid > 0 ? wsum[wid - 1] : 0);
    if (i < NN) { g_rowptr[i + 1] = incl; g_wptr[i] = incl - v; }
    carry += wsum[31];
    __syncthreads();
  }
  if (tid == 0) g_rowptr[0] = 0;
}

// ---------------- launch 3: edge scatter into CSR + eaW precompute (fp16) ----------------
__global__ __launch_bounds__(256) void scatter_kernel(
    const int* __restrict__ ei, const float* __restrict__ ea,
    const float* __restrict__ W1m)
{
  __shared__ float sWea[4 * 64];
  int tid = threadIdx.x;
  if (tid < 64) ((float4*)sWea)[tid] = ((const float4*)(W1m + 32 * 64))[tid];
  __syncthreads();
  int e = blockIdx.x * 256 + tid;
  if (e < EE) {
    int d = ei[EE + e];
    int pos = atomicAdd(&g_wptr[d], 1);
    g_src_sorted[pos] = ei[e];
    float4 a = ((const float4*)ea)[e];
    __half2* dst = &g_eaw[pos * 32];
    #pragma unroll
    for (int c = 0; c < 32; c++) {
      float e0 = a.x * sWea[c]       + a.y * sWea[64 + c]
               + a.z * sWea[128 + c] + a.w * sWea[192 + c];
      float e1 = a.x * sWea[32 + c]       + a.y * sWea[96 + c]
               + a.z * sWea[160 + c] + a.w * sWea[224 + c];
      dst[c] = __floats2half2_rn(e0, e1);
    }
  }
}

// ---------------- launch 4..243: fused per-stage kernel, 2 nodes per warp ----------------
__global__ __launch_bounds__(256) void edge_node_kernel(
    int s, int it, int sub, int outrow, int pbuf,
    const float* __restrict__ t,
    const float* __restrict__ W1m, const float* __restrict__ W2m,
    const float* __restrict__ b2m, const float* __restrict__ W1n,
    const float* __restrict__ W2n, const float* __restrict__ b2n,
    const float* __restrict__ b1m)
{
  __shared__ float sW2m[64 * 16];
  __shared__ float sW1nx[16 * 64];
  __shared__ float sW1na[16 * 64];
  __shared__ float sW2n[64 * 16];
  __shared__ float sW1m[32 * 64];
  __shared__ float swt[64];
  __shared__ float sb1m[64];
  __shared__ float sb2m[16], sb2n[16];
  __shared__ float sbuf[8][128];   // 2 nodes x 64 ch per warp
  __shared__ float sxi[8][32];     // 2 nodes x 16
  __shared__ float sagg[8][32];
  __shared__ float sxin[8][32];

  int tid = threadIdx.x;
  for (int i = tid; i < 256; i += 256) {
    ((float4*)sW2m)[i]  = ((const float4*)W2m)[i];
    ((float4*)sW1nx)[i] = ((const float4*)W1n)[i];
    ((float4*)sW1na)[i] = ((const float4*)(W1n + 1024))[i];
    ((float4*)sW2n)[i]  = ((const float4*)W2n)[i];
  }
  for (int i = tid; i < 512; i += 256) ((float4*)sW1m)[i] = ((const float4*)W1m)[i];
  if (tid < 16) ((float4*)swt)[tid]  = ((const float4*)(W1n + 208 * 64))[tid];
  if (tid >= 16 && tid < 32) ((float4*)sb1m)[tid - 16] = ((const float4*)b1m)[tid - 16];
  if (tid >= 32 && tid < 36) ((float4*)sb2m)[tid - 32] = ((const float4*)b2m)[tid - 32];
  if (tid >= 36 && tid < 40) ((float4*)sb2n)[tid - 36] = ((const float4*)b2n)[tid - 36];

  int w = tid >> 5, lane = tid & 31;
  int n0 = (blockIdx.x * 8 + w) * 2;   // warp owns nodes n0, n0+1 (contiguous)
  int n1 = n0 + 1;
  sxi[w][lane] = g_xi[n0 * 16 + lane];   // 32 floats = both nodes' xi, coalesced
  __syncthreads();

  float tA = t[it], tB = t[it + 1];
  float dti = (tB - tA) * 0.25f;
  float ti = tA + (float)sub * dti + c_C[s] * dti;

  const __half2* __restrict__ U = &g_uv[pbuf][0];
  const __half2* __restrict__ EW = &g_eaw[0];
  float v0a = g_v[n0 * 64 + lane], v1a = g_v[n0 * 64 + 32 + lane];
  float v0b = g_v[n1 * 64 + lane], v1b = g_v[n1 * 64 + 32 + lane];

  int bega = g_rowptr[n0];
  int begb = g_rowptr[n0 + 1];
  int endb = g_rowptr[n0 + 2];

  float acc0a = 0.f, acc1a = 0.f, acc0b = 0.f, acc1b = 0.f;

  // ---- edge loop node0 (2-deep pipeline) ----
  {
    int e = bega, end = begb;
    __half2 ewc = __float2half2_rn(0.f), uhc = __float2half2_rn(0.f);
    if (e < end) {
      int srcc = g_src_sorted[e];
      ewc = EW[e * 32 + lane];
      uhc = U[srcc * 32 + lane];
    }
    for (; e < end; e++) {
      int e1 = e + 1;
      __half2 ewn = ewc, uhn = uhc;
      if (e1 < end) {
        int srcn = g_src_sorted[e1];
        ewn = EW[e1 * 32 + lane];
        uhn = U[srcn * 32 + lane];
      }
      float2 sf = __half22float2(__hadd2(uhc, ewc));
      acc0a += tanha(sf.x + v0a);
      acc1a += tanha(sf.y + v1a);
      ewc = ewn; uhc = uhn;
    }
  }
  // ---- edge loop node1 ----
  {
    int e = begb, end = endb;
    __half2 ewc = __float2half2_rn(0.f), uhc = __float2half2_rn(0.f);
    if (e < end) {
      int srcc = g_src_sorted[e];
      ewc = EW[e * 32 + lane];
      uhc = U[srcc * 32 + lane];
    }
    for (; e < end; e++) {
      int e1 = e + 1;
      __half2 ewn = ewc, uhn = uhc;
      if (e1 < end) {
        int srcn = g_src_sorted[e1];
        ewn = EW[e1 * 32 + lane];
        uhn = U[srcn * 32 + lane];
      }
      float2 sf = __half22float2(__hadd2(uhc, ewc));
      acc0b += tanha(sf.x + v0b);
      acc1b += tanha(sf.y + v1b);
      ewc = ewn; uhc = uhn;
    }
  }

  // ---- agg for both nodes: shared W2m reads, float4 h-vector broadcasts ----
  sbuf[w][lane]      = acc0a;
  sbuf[w][32 + lane] = acc1a;
  sbuf[w][64 + lane] = acc0b;
  sbuf[w][96 + lane] = acc1b;
  __syncwarp();
  int j = lane & 15;
  int cbase = (lane < 16) ? 0 : 32;
  float pa = 0.f, pb = 0.f;
  #pragma unroll
  for (int c4 = 0; c4 < 8; c4++) {
    float4 ha = ((const float4*)(sbuf[w] + cbase))[c4];
    float4 hb = ((const float4*)(sbuf[w] + 64 + cbase))[c4];
    float w0 = sW2m[(cbase + c4 * 4 + 0) * 16 + j];
    float w1 = sW2m[(cbase + c4 * 4 + 1) * 16 + j];
    float w2 = sW2m[(cbase + c4 * 4 + 2) * 16 + j];
    float w3 = sW2m[(cbase + c4 * 4 + 3) * 16 + j];
    pa += ha.x * w0 + ha.y * w1 + ha.z * w2 + ha.w * w3;
    pb += hb.x * w0 + hb.y * w1 + hb.z * w2 + hb.w * w3;
  }
  pa += __shfl_xor_sync(0xffffffffu, pa, 16);
  pb += __shfl_xor_sync(0xffffffffu, pb, 16);
  {
    int r = lane >> 4;
    float deg = (float)(r ? (endb - begb) : (begb - bega));
    float pv = r ? pb : pa;
    sagg[w][lane] = pv + deg * sb2m[j];   // lane = r*16+j
  }
  __syncwarp();

  // ---- hidden layer for both nodes, shared weight reads ----
  float h0a = g_augproj[n0 * 64 + lane]      + ti * swt[lane];
  float h1a = g_augproj[n0 * 64 + 32 + lane] + ti * swt[32 + lane];
  float h0b = g_augproj[n1 * 64 + lane]      + ti * swt[lane];
  float h1b = g_augproj[n1 * 64 + 32 + lane] + ti * swt[32 + lane];
  #pragma unroll
  for (int i = 0; i < 16; i++) {
    float wxa = sW1nx[i * 64 + lane], wxb = sW1nx[i * 64 + 32 + lane];
    float waa = sW1na[i * 64 + lane], wab = sW1na[i * 64 + 32 + lane];
    float xva = sxi[w][i],  xvb = sxi[w][16 + i];
    float ava = sagg[w][i], avb = sagg[w][16 + i];
    h0a += xva * wxa + ava * waa;
    h1a += xva * wxb + ava * wab;
    h0b += xvb * wxa + avb * waa;
    h1b += xvb * wxb + avb * wab;
  }
  __syncwarp();
  sbuf[w][lane]      = tanha(h0a);
  sbuf[w][32 + lane] = tanha(h1a);
  sbuf[w][64 + lane] = tanha(h0b);
  sbuf[w][96 + lane] = tanha(h1b);
  __syncwarp();

  // ---- output layer for both nodes ----
  float oa = 0.f, ob = 0.f;
  #pragma unroll
  for (int c4 = 0; c4 < 8; c4++) {
    float4 ha = ((const float4*)(sbuf[w] + cbase))[c4];
    float4 hb = ((const float4*)(sbuf[w] + 64 + cbase))[c4];
    float w0 = sW2n[(cbase + c4 * 4 + 0) * 16 + j];
    float w1 = sW2n[(cbase + c4 * 4 + 1) * 16 + j];
    float w2 = sW2n[(cbase + c4 * 4 + 2) * 16 + j];
    float w3 = sW2n[(cbase + c4 * 4 + 3) * 16 + j];
    oa += ha.x * w0 + ha.y * w1 + ha.z * w2 + ha.w * w3;
    ob += hb.x * w0 + hb.y * w1 + hb.z * w2 + hb.w * w3;
  }
  oa += __shfl_xor_sync(0xffffffffu, oa, 16);
  ob += __shfl_xor_sync(0xffffffffu, ob, 16);

  // ---- epilogue: all 32 lanes active; lane = r*16 + j handles (node n0+r, col j) ----
  {
    int r = lane >> 4;
    int idx = (n0 + r) * 16 + j;            // lanes cover 32 contiguous floats
    float kval = (r ? ob : oa) + sb2n[j];
    g_k[s][idx] = kval;
    int row = (s < 5) ? s + 1 : 6;
    float acc = c_coef[row][s] * kval;
    #pragma unroll
    for (int jj = 0; jj < 5; jj++) {
      if (jj < s) acc += c_coef[row][jj] * g_k[jj][idx];
    }
    float xv = g_x0[idx] + dti * acc;
    if (s == 5) {
      g_x0[idx] = xv;
      if (outrow >= 0) g_ys[outrow * NF + idx] = xv;
    }
    g_xi[idx] = xv;
    sxin[w][lane] = xv;                      // lane = r*16+j
  }
  __syncwarp();

  // ---- u/v projection for both nodes, shared weight reads ----
  float u0a = 0.f, u1a = 0.f, u0b = 0.f, u1b = 0.f;
  float nv0a = sb1m[lane], nv1a = sb1m[32 + lane];
  float nv0b = nv0a, nv1b = nv1a;
  #pragma unroll
  for (int i = 0; i < 16; i++) {
    float wu0 = sW1m[i * 64 + lane],        wu1 = sW1m[i * 64 + 32 + lane];
    float wv0 = sW1m[(16 + i) * 64 + lane], wv1 = sW1m[(16 + i) * 64 + 32 + lane];
    float xa = sxin[w][i], xb = sxin[w][16 + i];
    u0a  += xa * wu0;  u1a  += xa * wu1;
    nv0a += xa * wv0;  nv1a += xa * wv1;
    u0b  += xb * wu0;  u1b  += xb * wu1;
    nv0b += xb * wv0;  nv1b += xb * wv1;
  }
  g_uv[pbuf ^ 1][n0 * 32 + lane] = __floats2half2_rn(u0a, u1a);
  g_uv[pbuf ^ 1][n1 * 32 + lane] = __floats2half2_rn(u0b, u1b);
  g_v[n0 * 64 + lane] = nv0a;
  g_v[n0 * 64 + 32 + lane] = nv1a;
  g_v[n1 * 64 + lane] = nv0b;
  g_v[n1 * 64 + 32 + lane] = nv1b;
}

__global__ __launch_bounds__(256) void gather_out_kernel(
    const int* __restrict__ mask_idx, float* __restrict__ out)
{
  int idx = blockIdx.x * 256 + threadIdx.x;
  if (idx < TOUT * NF) {
    int row = idx / NF;
    int rem = idx - row * NF;
    out[idx] = g_ys[mask_idx[row] * NF + rem];
  }
}

// ---------------- launcher ----------------
extern "C" void kernel_launch(void* const* d_in, const int* in_sizes, int n_in,
                              void* d_out, int out_size)
{
  const float* x_hist   = (const float*)d_in[0];
  const float* x_mask   = (const float*)d_in[1];
  const int*   ei       = (const int*)d_in[2];
  const float* ea       = (const float*)d_in[3];
  const float* t        = (const float*)d_in[4];
  const int*   mask_idx = (const int*)d_in[5];
  const float* W1m = (const float*)d_in[6];
  const float* b1m = (const float*)d_in[7];
  const float* W2m = (const float*)d_in[8];
  const float* b2m = (const float*)d_in[9];
  const float* W1n = (const float*)d_in[10];
  const float* b1n = (const float*)d_in[11];
  const float* W2n = (const float*)d_in[12];
  const float* b2n = (const float*)d_in[13];
  float* out = (float*)d_out;

  // exactly 3 setup launches -> the 4th process launch is edge_node_kernel (ncu target)
  combo_kernel<<<NN / 4, 256>>>(x_hist, x_mask, W1m, b1m, W1n, b1n);   // 1
  histscan_kernel<<<1, 1024>>>(ei);                                     // 2
  scatter_kernel<<<(EE + 255) / 256, 256>>>(ei, ea, W1m);               // 3

  int L = 0;
  for (int it = 0; it < TOUT; it++) {
    for (int sub = 0; sub < 4; sub++) {
      for (int s = 0; s < 6; s++) {
        int outrow = (s == 5 && sub == 3) ? it : -1;
        edge_node_kernel<<<NN / 16, 256>>>(s, it, sub, outrow, L & 1,
                                           t, W1m, W2m, b2m, W1n, W2n, b2n, b1m);
        L++;
      }
    }
  }

  gather_out_kernel<<<(TOUT * NF + 255) / 256, 256>>>(mask_idx, out);
}

// round 14
// speedup vs baseline: 1.4345x; 1.4345x over previous
#include <cuda_runtime.h>
#include <cuda_fp16.h>

#define NN 50000
#define FF 16
#define EE 800000
#define HH 64
#define TOUT 10
#define NF (NN*FF)

// ---------------- device state ----------------
__device__ float   g_x0[NF];
__device__ float   g_xi[NF];
__device__ float   g_k[6][NF];
__device__ __half2 g_uv[2][NN*32];   // packed u: (.x=ch lane, .y=ch lane+32), double-buffered
__device__ float   g_v[NN*HH];
__device__ float   g_augproj[NN*HH];
__device__ float   g_ys[TOUT*NF];
__device__ int     g_deg[NN];
__device__ int     g_rowptr[NN+1];
__device__ int     g_wptr[NN];
__device__ int     g_src_sorted[EE];
__device__ float4  g_ea_sorted[EE];

// DOPRI5 coefficients. Row 0 unused, rows 1..5 = A[0..4], row 6 = B.
__constant__ float c_coef[7][6] = {
  {0.f,0.f,0.f,0.f,0.f,0.f},
  {(float)(0.2), 0.f,0.f,0.f,0.f,0.f},
  {(float)(3.0/40.0), (float)(9.0/40.0), 0.f,0.f,0.f,0.f},
  {(float)(44.0/45.0), (float)(-56.0/15.0), (float)(32.0/9.0), 0.f,0.f,0.f},
  {(float)(19372.0/6561.0), (float)(-25360.0/2187.0), (float)(64448.0/6561.0), (float)(-212.0/729.0), 0.f,0.f},
  {(float)(9017.0/3168.0), (float)(-355.0/33.0), (float)(46732.0/5247.0), (float)(49.0/176.0), (float)(-5103.0/18656.0), 0.f},
  {(float)(35.0/384.0), 0.f, (float)(500.0/1113.0), (float)(125.0/192.0), (float)(-2187.0/6784.0), (float)(11.0/84.0)}
};
__constant__ float c_C[6] = {0.f, 0.2f, 0.3f, 0.8f, (float)(8.0/9.0), 1.f};

__device__ __forceinline__ float tanha(float x) {
  float r;
  asm("tanh.approx.f32 %0, %1;" : "=f"(r) : "f"(x));
  return r;
}

// ---------------- launch 1: combo = state init + augproj + u/v projection + deg zero ----------------
__global__ __launch_bounds__(256) void combo_kernel(
    const float* __restrict__ xh, const float* __restrict__ xm,
    const float* __restrict__ W1m, const float* __restrict__ b1m,
    const float* __restrict__ W1n, const float* __restrict__ b1n)
{
  __shared__ float saug[4][176];
  __shared__ float sW[32 * 64];
  __shared__ float sxi[4][16];
  __shared__ float sb[64];
  int b = blockIdx.x;
  int tid = threadIdx.x;
  int gid = b * 256 + tid;
  if (gid < NN) g_deg[gid] = 0;
  int ln = tid >> 6;
  int ch = tid & 63;
  int n = b * 4 + ln;
  #pragma unroll
  for (int i = tid; i < 512; i += 256) ((float4*)sW)[i] = ((const float4*)W1m)[i];
  if (tid < 16) ((float4*)sb)[tid] = ((const float4*)b1m)[tid];
  if (ch < 16) {
    int f = ch;
    float xs[10], ms[10];
    float sm = 0.f, cm = 0.f;
    #pragma unroll
    for (int tt = 0; tt < 10; tt++) {
      xs[tt] = xh[(tt * NN + n) * FF + f];
      ms[tt] = xm[tt * NN + n];
      sm += xs[tt] * ms[tt];
      cm += ms[tt];
    }
    float cnt = fmaxf(cm, 1.0f);
    float mean = sm / cnt;
    float var = 0.f;
    #pragma unroll
    for (int tt = 0; tt < 10; tt++) { float d = xs[tt] - mean; var += d * d * ms[tt]; }
    var /= cnt;
    #pragma unroll
    for (int tt = 0; tt < 9; tt++)
      saug[ln][tt * 16 + f] = (xs[tt + 1] - xs[tt]) * (ms[tt + 1] * ms[tt]);
    saug[ln][144 + f] = mean;
    saug[ln][160 + f] = var;
    int idx = n * 16 + f;
    float xv = xs[9];
    g_x0[idx] = xv;
    g_xi[idx] = xv;
    sxi[ln][f] = xv;
  }
  __syncthreads();
  {
    float acc = b1n[ch];
    #pragma unroll 8
    for (int r = 0; r < 176; r++)
      acc += saug[ln][r] * W1n[(32 + r) * 64 + ch];
    g_augproj[n * 64 + ch] = acc;
  }
  if (ch < 32) {
    int lane = ch;
    float u0 = 0.f, u1 = 0.f;
    float v0 = sb[lane], v1 = sb[32 + lane];
    #pragma unroll
    for (int i = 0; i < 16; i++) {
      float xv = sxi[ln][i];
      u0 += xv * sW[i * 64 + lane];
      u1 += xv * sW[i * 64 + 32 + lane];
      v0 += xv * sW[(16 + i) * 64 + lane];
      v1 += xv * sW[(16 + i) * 64 + 32 + lane];
    }
    g_uv[0][n * 32 + lane] = __floats2half2_rn(u0, u1);
    g_v[n * 64 + lane] = v0;
    g_v[n * 64 + 32 + lane] = v1;
  }
}

// ---------------- launch 2: single-block histogram + rowptr scan ----------------
__global__ __launch_bounds__(1024) void histscan_kernel(const int* __restrict__ ei) {
  __shared__ int wsum[32];
  int tid = threadIdx.x, lane = tid & 31, wid = tid >> 5;
  for (int e = tid; e < EE; e += 1024)
    atomicAdd(&g_deg[ei[EE + e]], 1);
  __syncthreads();
  int carry = 0;
  for (int base = 0; base < NN; base += 1024) {
    int i = base + tid;
    int v = (i < NN) ? g_deg[i] : 0;
    int x = v;
    #pragma unroll
    for (int o = 1; o < 32; o <<= 1) { int y = __shfl_up_sync(0xffffffffu, x, o); if (lane >= o) x += y; }
    if (lane == 31) wsum[wid] = x;
    __syncthreads();
    if (wid == 0) {
      int s = wsum[lane];
      #pragma unroll
      for (int o = 1; o < 32; o <<= 1) { int y = __shfl_up_sync(0xffffffffu, s, o); if (lane >= o) s += y; }
      wsum[lane] = s;
    }
    __syncthreads();
    int incl = x + carry + (wid > 0 ? wsum[wid - 1] : 0);
    if (i < NN) { g_rowptr[i + 1] = incl; g_wptr[i] = incl - v; }
    carry += wsum[31];
    __syncthreads();
  }
  if (tid == 0) g_rowptr[0] = 0;
}

// ---------------- launch 3: edge scatter into CSR ----------------
__global__ __launch_bounds__(256) void scatter_kernel(
    const int* __restrict__ ei, const float* __restrict__ ea)
{
  int e = blockIdx.x * 256 + threadIdx.x;
  if (e < EE) {
    int d = ei[EE + e];
    int pos = atomicAdd(&g_wptr[d], 1);
    g_src_sorted[pos] = ei[e];
    g_ea_sorted[pos] = ((const float4*)ea)[e];
  }
}

// ---------------- launch 4..243: fused per-stage kernel, 2 nodes per warp ----------------
__global__ __launch_bounds__(256) void edge_node_kernel(
    int s, int it, int sub, int outrow, int pbuf,
    const float* __restrict__ t,
    const float* __restrict__ W1m, const float* __restrict__ W2m,
    const float* __restrict__ b2m, const float* __restrict__ W1n,
    const float* __restrict__ W2n, const float* __restrict__ b2n,
    const float* __restrict__ b1m)
{
  __shared__ float sWea[4 * 64];
  __shared__ float sW2m[64 * 16];
  __shared__ float sW1nx[16 * 64];
  __shared__ float sW1na[16 * 64];
  __shared__ float sW2n[64 * 16];
  __shared__ float sW1m[32 * 64];
  __shared__ float swt[64];
  __shared__ float sb1m[64];
  __shared__ float sb2m[16], sb2n[16];
  __shared__ float sbuf[8][128];   // 2 nodes x 64 ch per warp
  __shared__ float sxi[8][32];     // 2 nodes x 16
  __shared__ float sagg[8][32];
  __shared__ float sxin[8][32];

  int tid = threadIdx.x;
  if (tid < 64)  ((float4*)sWea)[tid] = ((const float4*)(W1m + 32 * 64))[tid];
  for (int i = tid; i < 256; i += 256) {
    ((float4*)sW2m)[i]  = ((const float4*)W2m)[i];
    ((float4*)sW1nx)[i] = ((const float4*)W1n)[i];
    ((float4*)sW1na)[i] = ((const float4*)(W1n + 1024))[i];
    ((float4*)sW2n)[i]  = ((const float4*)W2n)[i];
  }
  for (int i = tid; i < 512; i += 256) ((float4*)sW1m)[i] = ((const float4*)W1m)[i];
  if (tid < 16) ((float4*)swt)[tid]  = ((const float4*)(W1n + 208 * 64))[tid];
  if (tid >= 16 && tid < 32) ((float4*)sb1m)[tid - 16] = ((const float4*)b1m)[tid - 16];
  if (tid >= 32 && tid < 36) ((float4*)sb2m)[tid - 32] = ((const float4*)b2m)[tid - 32];
  if (tid >= 36 && tid < 40) ((float4*)sb2n)[tid - 36] = ((const float4*)b2n)[tid - 36];

  int w = tid >> 5, lane = tid & 31;
  int n0 = (blockIdx.x * 8 + w) * 2;   // warp owns nodes n0, n0+1 (contiguous)
  int n1 = n0 + 1;
  sxi[w][lane] = g_xi[n0 * 16 + lane];   // 32 floats = both nodes' xi, coalesced
  __syncthreads();

  float tA = t[it], tB = t[it + 1];
  float dti = (tB - tA) * 0.25f;
  float ti = tA + (float)sub * dti + c_C[s] * dti;

  const __half2* __restrict__ U = &g_uv[pbuf][0];
  float v0a = g_v[n0 * 64 + lane], v1a = g_v[n0 * 64 + 32 + lane];
  float v0b = g_v[n1 * 64 + lane], v1b = g_v[n1 * 64 + 32 + lane];
  float wx0 = sWea[lane],        wx1 = sWea[32 + lane];
  float wy0 = sWea[64 + lane],   wy1 = sWea[96 + lane];
  float wz0 = sWea[128 + lane],  wz1 = sWea[160 + lane];
  float ww0 = sWea[192 + lane],  ww1 = sWea[224 + lane];

  int bega = g_rowptr[n0];
  int begb = g_rowptr[n0 + 1];
  int endb = g_rowptr[n0 + 2];
  int da = begb - bega, db = endb - begb;
  int m = (da < db) ? da : db;

  float acc0a = 0.f, acc1a = 0.f, acc0b = 0.f, acc1b = 0.f;

  // ---- interleaved edge processing: both nodes per iteration (4+ loads in flight) ----
  #pragma unroll 2
  for (int i = 0; i < m; i++) {
    int ea_ = bega + i, eb_ = begb + i;
    int sa = g_src_sorted[ea_];
    int sb_ = g_src_sorted[eb_];
    float4 aa = g_ea_sorted[ea_];
    float4 ab = g_ea_sorted[eb_];
    __half2 uha = U[sa * 32 + lane];
    __half2 uhb = U[sb_ * 32 + lane];
    float2 ufa = __half22float2(uha);
    float2 ufb = __half22float2(uhb);
    float a0 = ufa.x + v0a + aa.x * wx0 + aa.y * wy0 + aa.z * wz0 + aa.w * ww0;
    float a1 = ufa.y + v1a + aa.x * wx1 + aa.y * wy1 + aa.z * wz1 + aa.w * ww1;
    float b0 = ufb.x + v0b + ab.x * wx0 + ab.y * wy0 + ab.z * wz0 + ab.w * ww0;
    float b1 = ufb.y + v1b + ab.x * wx1 + ab.y * wy1 + ab.z * wz1 + ab.w * ww1;
    acc0a += tanha(a0);
    acc1a += tanha(a1);
    acc0b += tanha(b0);
    acc1b += tanha(b1);
  }
  // ---- tail: remaining edges of the longer node ----
  #pragma unroll 2
  for (int e = bega + m; e < begb; e++) {
    int sa = g_src_sorted[e];
    float4 aa = g_ea_sorted[e];
    float2 ufa = __half22float2(U[sa * 32 + lane]);
    float a0 = ufa.x + v0a + aa.x * wx0 + aa.y * wy0 + aa.z * wz0 + aa.w * ww0;
    float a1 = ufa.y + v1a + aa.x * wx1 + aa.y * wy1 + aa.z * wz1 + aa.w * ww1;
    acc0a += tanha(a0);
    acc1a += tanha(a1);
  }
  #pragma unroll 2
  for (int e = begb + m; e < endb; e++) {
    int sb_ = g_src_sorted[e];
    float4 ab = g_ea_sorted[e];
    float2 ufb = __half22float2(U[sb_ * 32 + lane]);
    float b0 = ufb.x + v0b + ab.x * wx0 + ab.y * wy0 + ab.z * wz0 + ab.w * ww0;
    float b1 = ufb.y + v1b + ab.x * wx1 + ab.y * wy1 + ab.z * wz1 + ab.w * ww1;
    acc0b += tanha(b0);
    acc1b += tanha(b1);
  }

  // ---- agg for both nodes: shared W2m reads, float4 h-vector broadcasts ----
  sbuf[w][lane]      = acc0a;
  sbuf[w][32 + lane] = acc1a;
  sbuf[w][64 + lane] = acc0b;
  sbuf[w][96 + lane] = acc1b;
  __syncwarp();
  int j = lane & 15;
  int cbase = (lane < 16) ? 0 : 32;
  float pa = 0.f, pb = 0.f;
  #pragma unroll
  for (int c4 = 0; c4 < 8; c4++) {
    float4 ha = ((const float4*)(sbuf[w] + cbase))[c4];
    float4 hb = ((const float4*)(sbuf[w] + 64 + cbase))[c4];
    float w0 = sW2m[(cbase + c4 * 4 + 0) * 16 + j];
    float w1 = sW2m[(cbase + c4 * 4 + 1) * 16 + j];
    float w2 = sW2m[(cbase + c4 * 4 + 2) * 16 + j];
    float w3 = sW2m[(cbase + c4 * 4 + 3) * 16 + j];
    pa += ha.x * w0 + ha.y * w1 + ha.z * w2 + ha.w * w3;
    pb += hb.x * w0 + hb.y * w1 + hb.z * w2 + hb.w * w3;
  }
  pa += __shfl_xor_sync(0xffffffffu, pa, 16);
  pb += __shfl_xor_sync(0xffffffffu, pb, 16);
  {
    int r = lane >> 4;
    float deg = (float)(r ? db : da);
    float pv = r ? pb : pa;
    sagg[w][lane] = pv + deg * sb2m[j];   // lane = r*16+j
  }
  __syncwarp();

  // ---- hidden layer for both nodes, shared weight reads ----
  float h0a = g_augproj[n0 * 64 + lane]      + ti * swt[lane];
  float h1a = g_augproj[n0 * 64 + 32 + lane] + ti * swt[32 + lane];
  float h0b = g_augproj[n1 * 64 + lane]      + ti * swt[lane];
  float h1b = g_augproj[n1 * 64 + 32 + lane] + ti * swt[32 + lane];
  #pragma unroll
  for (int i = 0; i < 16; i++) {
    float wxa = sW1nx[i * 64 + lane], wxb = sW1nx[i * 64 + 32 + lane];
    float waa = sW1na[i * 64 + lane], wab = sW1na[i * 64 + 32 + lane];
    float xva = sxi[w][i],  xvb = sxi[w][16 + i];
    float ava = sagg[w][i], avb = sagg[w][16 + i];
    h0a += xva * wxa + ava * waa;
    h1a += xva * wxb + ava * wab;
    h0b += xvb * wxa + avb * waa;
    h1b += xvb * wxb + avb * wab;
  }
  __syncwarp();
  sbuf[w][lane]      = tanha(h0a);
  sbuf[w][32 + lane] = tanha(h1a);
  sbuf[w][64 + lane] = tanha(h0b);
  sbuf[w][96 + lane] = tanha(h1b);
  __syncwarp();

  // ---- output layer for both nodes ----
  float oa = 0.f, ob = 0.f;
  #pragma unroll
  for (int c4 = 0; c4 < 8; c4++) {
    float4 ha = ((const float4*)(sbuf[w] + cbase))[c4];
    float4 hb = ((const float4*)(sbuf[w] + 64 + cbase))[c4];
    float w0 = sW2n[(cbase + c4 * 4 + 0) * 16 + j];
    float w1 = sW2n[(cbase + c4 * 4 + 1) * 16 + j];
    float w2 = sW2n[(cbase + c4 * 4 + 2) * 16 + j];
    float w3 = sW2n[(cbase + c4 * 4 + 3) * 16 + j];
    oa += ha.x * w0 + ha.y * w1 + ha.z * w2 + ha.w * w3;
    ob += hb.x * w0 + hb.y * w1 + hb.z * w2 + hb.w * w3;
  }
  oa += __shfl_xor_sync(0xffffffffu, oa, 16);
  ob += __shfl_xor_sync(0xffffffffu, ob, 16);

  // ---- epilogue: all 32 lanes active; lane = r*16 + j handles (node n0+r, col j) ----
  {
    int r = lane >> 4;
    int idx = (n0 + r) * 16 + j;            // lanes cover 32 contiguous floats
    float kval = (r ? ob : oa) + sb2n[j];
    g_k[s][idx] = kval;
    int row = (s < 5) ? s + 1 : 6;
    float acc = c_coef[row][s] * kval;
    #pragma unroll
    for (int jj = 0; jj < 5; jj++) {
      if (jj < s) acc += c_coef[row][jj] * g_k[jj][idx];
    }
    float xv = g_x0[idx] + dti * acc;
    if (s == 5) {
      g_x0[idx] = xv;
      if (outrow >= 0) g_ys[outrow * NF + idx] = xv;
    }
    g_xi[idx] = xv;
    sxin[w][lane] = xv;                      // lane = r*16+j
  }
  __syncwarp();

  // ---- u/v projection for both nodes, shared weight reads ----
  float u0a = 0.f, u1a = 0.f, u0b = 0.f, u1b = 0.f;
  float nv0a = sb1m[lane], nv1a = sb1m[32 + lane];
  float nv0b = nv0a, nv1b = nv1a;
  #pragma unroll
  for (int i = 0; i < 16; i++) {
    float wu0 = sW1m[i * 64 + lane],        wu1 = sW1m[i * 64 + 32 + lane];
    float wv0 = sW1m[(16 + i) * 64 + lane], wv1 = sW1m[(16 + i) * 64 + 32 + lane];
    float xa = sxin[w][i], xb = sxin[w][16 + i];
    u0a  += xa * wu0;  u1a  += xa * wu1;
    nv0a += xa * wv0;  nv1a += xa * wv1;
    u0b  += xb * wu0;  u1b  += xb * wu1;
    nv0b += xb * wv0;  nv1b += xb * wv1;
  }
  g_uv[pbuf ^ 1][n0 * 32 + lane] = __floats2half2_rn(u0a, u1a);
  g_uv[pbuf ^ 1][n1 * 32 + lane] = __floats2half2_rn(u0b, u1b);
  g_v[n0 * 64 + lane] = nv0a;
  g_v[n0 * 64 + 32 + lane] = nv1a;
  g_v[n1 * 64 + lane] = nv0b;
  g_v[n1 * 64 + 32 + lane] = nv1b;
}

__global__ __launch_bounds__(256) void gather_out_kernel(
    const int* __restrict__ mask_idx, float* __restrict__ out)
{
  int idx = blockIdx.x * 256 + threadIdx.x;
  if (idx < TOUT * NF) {
    int row = idx / NF;
    int rem = idx - row * NF;
    out[idx] = g_ys[mask_idx[row] * NF + rem];
  }
}

// ---------------- launcher ----------------
extern "C" void kernel_launch(void* const* d_in, const int* in_sizes, int n_in,
                              void* d_out, int out_size)
{
  const float* x_hist   = (const float*)d_in[0];
  const float* x_mask   = (const float*)d_in[1];
  const int*   ei       = (const int*)d_in[2];
  const float* ea       = (const float*)d_in[3];
  const float* t        = (const float*)d_in[4];
  const int*   mask_idx = (const int*)d_in[5];
  const float* W1m = (const float*)d_in[6];
  const float* b1m = (const float*)d_in[7];
  const float* W2m = (const float*)d_in[8];
  const float* b2m = (const float*)d_in[9];
  const float* W1n = (const float*)d_in[10];
  const float* b1n = (const float*)d_in[11];
  const float* W2n = (const float*)d_in[12];
  const float* b2n = (const float*)d_in[13];
  float* out = (float*)d_out;

  // exactly 3 setup launches -> the 4th process launch is edge_node_kernel (ncu target)
  combo_kernel<<<NN / 4, 256>>>(x_hist, x_mask, W1m, b1m, W1n, b1n);   // 1
  histscan_kernel<<<1, 1024>>>(ei);                                     // 2
  scatter_kernel<<<(EE + 255) / 256, 256>>>(ei, ea);                    // 3

  int L = 0;
  for (int it = 0; it < TOUT; it++) {
    for (int sub = 0; sub < 4; sub++) {
      for (int s = 0; s < 6; s++) {
        int outrow = (s == 5 && sub == 3) ? it : -1;
        edge_node_kernel<<<NN / 16, 256>>>(s, it, sub, outrow, L & 1,
                                           t, W1m, W2m, b2m, W1n, W2n, b2n, b1m);
        L++;
      }
    }
  }

  gather_out_kernel<<<(TOUT * NF + 255) / 256, 256>>>(mask_idx, out);
}